// round 14
// baseline (speedup 1.0000x reference)
#include <cuda_runtime.h>

#define NN 4096
#define EE 16384
#define DD 13
#define RR 128
#define NP 4
#define HOSTRIDE 132
#define PBLK 8
#define PREPB 32
#define EPB  (EE / PBLK)
#define GCAP 2304

typedef unsigned long long u64;

__device__ int   g_groups[PBLK * GCAP];
__device__ int   g_cnt4[PBLK];
__device__ __align__(16) float g_T[NN * NP * RR];          // 8 MB stage-1 table
__device__ __align__(16) float g_hoT[3 * NP * DD * HOSTRIDE];

// k_main smem layout (floats)
#define S_HO   0
#define S_HOB  (3 * NP * DD * HOSTRIDE)
#define S_TOT  (S_HOB + 3 * NP * DD)      // 20748 floats ~ 83 KB

// ---------------- f32x2 packed helpers --------------------------------------
__device__ __forceinline__ u64 pk2(float lo, float hi) {
    u64 r; asm("mov.b64 %0,{%1,%2};" : "=l"(r) : "f"(lo), "f"(hi)); return r;
}
__device__ __forceinline__ u64 dup2(float v) {
    u64 r; asm("mov.b64 %0,{%1,%1};" : "=l"(r) : "f"(v)); return r;
}
__device__ __forceinline__ void up2(float& lo, float& hi, u64 v) {
    asm("mov.b64 {%0,%1},%2;" : "=f"(lo), "=f"(hi) : "l"(v));
}
__device__ __forceinline__ u64 fma2(u64 a, u64 b, u64 c) {
    u64 d; asm("fma.rn.f32x2 %0,%1,%2,%3;" : "=l"(d) : "l"(a), "l"(b), "l"(c)); return d;
}
__device__ __forceinline__ u64 mul2(u64 a, u64 b) {
    u64 d; asm("mul.rn.f32x2 %0,%1,%2;" : "=l"(d) : "l"(a), "l"(b)); return d;
}
__device__ __forceinline__ u64 add2(u64 a, u64 b) {
    u64 d; asm("add.rn.f32x2 %0,%1,%2;" : "=l"(d) : "l"(a), "l"(b)); return d;
}

// ---- prep: blocks 0-7 bucket-sort; blocks 8-31 build the stage-1 table T ----
__global__ void __launch_bounds__(1024, 1) k_prep(const int* __restrict__ et,
                                                  const float* __restrict__ nodes,
                                                  const float* __restrict__ bp_params,
                                                  const float* __restrict__ bp_bias,
                                                  const float* __restrict__ ho_params,
                                                  float* __restrict__ out) {
    __shared__ float s_bp[NP * DD * RR + NP * RR];  // weights + bias
    __shared__ int hist[64], bstart[64], cursor[64], gb[64], sc[64], sg[64];
    __shared__ short sorted[EPB];
    __shared__ unsigned char keys[EPB], skey[EPB];
    const int tid = threadIdx.x;
    const int bi  = blockIdx.x;
    const int lane = tid & 31;
    const int warp = tid >> 5;

    // bp weights to smem (needed by T-compute blocks; cheap for all)
    for (int i = tid; i < NP * DD * RR; i += 1024) s_bp[i] = bp_params[i];
    for (int i = tid; i < NP * RR; i += 1024)      s_bp[NP * DD * RR + i] = bp_bias[i];

    // shared jobs split over 32 blocks
    for (int i = tid; i < NN * DD / PREPB; i += 1024) out[bi * (NN * DD / PREPB) + i] = 0.f;
    {
        const int totalho = 3 * NP * RR * DD;   // 19968
        for (int i = bi * 1024 + tid; i < totalho; i += PREPB * 1024) {
            int d  = i % DD;
            int rd = i / DD;
            int r  = rd & (RR - 1);
            int sp = rd >> 7;
            g_hoT[(sp * DD + d) * HOSTRIDE + r] = ho_params[i];
        }
    }
    __syncthreads();

    if (bi >= PBLK) {
        // ---- T-table compute: batches of 4 nodes, fixed ty ------------------
        // batch id: [0, 4096): ty = bb>>10, n0 = (bb & 1023) * 4
        for (int bb = (bi - PBLK) * 32 + warp; bb < 4096; bb += (PREPB - PBLK) * 32) {
            const int ty = bb >> 10;
            const int n0 = (bb & 1023) << 2;
            const float* w = s_bp + ty * DD * RR;
            float4 bias = reinterpret_cast<const float4*>(s_bp + NP * DD * RR + ty * RR)[lane];
            float4 a0 = bias, a1 = bias, a2 = bias, a3 = bias;
#pragma unroll
            for (int d = 0; d < DD; d++) {
                float4 wv = reinterpret_cast<const float4*>(w + d * RR)[lane];
                float n0v = __ldg(nodes + (n0 + 0) * DD + d);
                float n1v = __ldg(nodes + (n0 + 1) * DD + d);
                float n2v = __ldg(nodes + (n0 + 2) * DD + d);
                float n3v = __ldg(nodes + (n0 + 3) * DD + d);
                a0.x = fmaf(n0v, wv.x, a0.x); a0.y = fmaf(n0v, wv.y, a0.y);
                a0.z = fmaf(n0v, wv.z, a0.z); a0.w = fmaf(n0v, wv.w, a0.w);
                a1.x = fmaf(n1v, wv.x, a1.x); a1.y = fmaf(n1v, wv.y, a1.y);
                a1.z = fmaf(n1v, wv.z, a1.z); a1.w = fmaf(n1v, wv.w, a1.w);
                a2.x = fmaf(n2v, wv.x, a2.x); a2.y = fmaf(n2v, wv.y, a2.y);
                a2.z = fmaf(n2v, wv.z, a2.z); a2.w = fmaf(n2v, wv.w, a2.w);
                a3.x = fmaf(n3v, wv.x, a3.x); a3.y = fmaf(n3v, wv.y, a3.y);
                a3.z = fmaf(n3v, wv.z, a3.z); a3.w = fmaf(n3v, wv.w, a3.w);
            }
            a0.x = fmaxf(a0.x, 0.f); a0.y = fmaxf(a0.y, 0.f); a0.z = fmaxf(a0.z, 0.f); a0.w = fmaxf(a0.w, 0.f);
            a1.x = fmaxf(a1.x, 0.f); a1.y = fmaxf(a1.y, 0.f); a1.z = fmaxf(a1.z, 0.f); a1.w = fmaxf(a1.w, 0.f);
            a2.x = fmaxf(a2.x, 0.f); a2.y = fmaxf(a2.y, 0.f); a2.z = fmaxf(a2.z, 0.f); a2.w = fmaxf(a2.w, 0.f);
            a3.x = fmaxf(a3.x, 0.f); a3.y = fmaxf(a3.y, 0.f); a3.z = fmaxf(a3.z, 0.f); a3.w = fmaxf(a3.w, 0.f);
            reinterpret_cast<float4*>(g_T + ((n0 + 0) * NP + ty) * RR)[lane] = a0;
            reinterpret_cast<float4*>(g_T + ((n0 + 1) * NP + ty) * RR)[lane] = a1;
            reinterpret_cast<float4*>(g_T + ((n0 + 2) * NP + ty) * RR)[lane] = a2;
            reinterpret_cast<float4*>(g_T + ((n0 + 3) * NP + ty) * RR)[lane] = a3;
        }
        return;
    }

    // ---- bucket sort (blocks 0-7) -------------------------------------------
    const int base = bi * EPB;
    for (int i = tid; i < GCAP; i += 1024) g_groups[bi * GCAP + i] = -1;

    if (tid < 64) hist[tid] = 0;
    __syncthreads();
    for (int i = tid; i < EPB; i += 1024) {
        int e = base + i;
        int k = __ldg(et + e * 3) * 16 + __ldg(et + e * 3 + 1) * 4 + __ldg(et + e * 3 + 2);
        keys[i] = (unsigned char)k;
        atomicAdd(&hist[k], 1);
    }
    __syncthreads();
    if (tid < 64) { sc[tid] = hist[tid]; sg[tid] = (hist[tid] + 3) >> 2; }
    __syncthreads();
    for (int off = 1; off < 64; off <<= 1) {
        int v1 = 0, v2 = 0;
        if (tid >= off && tid < 64) { v1 = sc[tid - off]; v2 = sg[tid - off]; }
        __syncthreads();
        if (tid >= off && tid < 64) { sc[tid] += v1; sg[tid] += v2; }
        __syncthreads();
    }
    if (tid < 64) {
        bstart[tid] = sc[tid] - hist[tid];
        cursor[tid] = sc[tid] - hist[tid];
        gb[tid]     = sg[tid] - ((hist[tid] + 3) >> 2);
        if (tid == 63) g_cnt4[bi] = sg[63];
    }
    __syncthreads();
    for (int i = tid; i < EPB; i += 1024) {
        int k = keys[i];
        int pos = atomicAdd(&cursor[k], 1);
        sorted[pos] = (short)i;
        skey[pos] = (unsigned char)k;
    }
    __syncthreads();
    for (int i = tid; i < EPB; i += 1024) {
        int k = skey[i];
        int r = i - bstart[k];
        g_groups[bi * GCAP + gb[k] * 4 + r] = base + (int)sorted[i];
    }
}

// ---- interleaved packed warp reduction of 2x13 f32x2 streams ----------------
__device__ __forceinline__ void tree13p2(u64* a, u64* b, int lane, u64& ra, u64& rb) {
    {
        u64 oa[13], ob[13];
#pragma unroll
        for (int i = 0; i < 13; i++) { oa[i] = __shfl_xor_sync(0xffffffffu, a[i], 16);
                                       ob[i] = __shfl_xor_sync(0xffffffffu, b[i], 16); }
        if (lane & 16) {
#pragma unroll
            for (int i = 0; i < 6; i++) { a[i] = add2(a[i + 7], oa[i + 7]); b[i] = add2(b[i + 7], ob[i + 7]); }
        } else {
#pragma unroll
            for (int i = 0; i < 7; i++) { a[i] = add2(a[i], oa[i]); b[i] = add2(b[i], ob[i]); }
        }
    }
    {
        u64 oa[7], ob[7];
#pragma unroll
        for (int i = 0; i < 7; i++) { oa[i] = __shfl_xor_sync(0xffffffffu, a[i], 8);
                                      ob[i] = __shfl_xor_sync(0xffffffffu, b[i], 8); }
        if (!(lane & 16)) {
            if (lane & 8) { a[0] = add2(a[4], oa[4]); a[1] = add2(a[5], oa[5]); a[2] = add2(a[6], oa[6]);
                            b[0] = add2(b[4], ob[4]); b[1] = add2(b[5], ob[5]); b[2] = add2(b[6], ob[6]); }
            else { a[0] = add2(a[0], oa[0]); a[1] = add2(a[1], oa[1]); a[2] = add2(a[2], oa[2]); a[3] = add2(a[3], oa[3]);
                   b[0] = add2(b[0], ob[0]); b[1] = add2(b[1], ob[1]); b[2] = add2(b[2], ob[2]); b[3] = add2(b[3], ob[3]); }
        } else {
            if (lane & 8) { a[0] = add2(a[3], oa[3]); a[1] = add2(a[4], oa[4]); a[2] = add2(a[5], oa[5]);
                            b[0] = add2(b[3], ob[3]); b[1] = add2(b[4], ob[4]); b[2] = add2(b[5], ob[5]); }
            else { a[0] = add2(a[0], oa[0]); a[1] = add2(a[1], oa[1]); a[2] = add2(a[2], oa[2]);
                   b[0] = add2(b[0], ob[0]); b[1] = add2(b[1], ob[1]); b[2] = add2(b[2], ob[2]); }
        }
    }
    {
        u64 oa[4], ob[4];
#pragma unroll
        for (int i = 0; i < 4; i++) { oa[i] = __shfl_xor_sync(0xffffffffu, a[i], 4);
                                      ob[i] = __shfl_xor_sync(0xffffffffu, b[i], 4); }
        bool four = ((lane & 24) == 0);
        if (lane & 4) {
            a[0] = add2(a[2], oa[2]); b[0] = add2(b[2], ob[2]);
            if (four) { a[1] = add2(a[3], oa[3]); b[1] = add2(b[3], ob[3]); }
        } else {
            a[0] = add2(a[0], oa[0]); a[1] = add2(a[1], oa[1]);
            b[0] = add2(b[0], ob[0]); b[1] = add2(b[1], ob[1]);
        }
    }
    {
        u64 oa0 = __shfl_xor_sync(0xffffffffu, a[0], 2);
        u64 oa1 = __shfl_xor_sync(0xffffffffu, a[1], 2);
        u64 ob0 = __shfl_xor_sync(0xffffffffu, b[0], 2);
        u64 ob1 = __shfl_xor_sync(0xffffffffu, b[1], 2);
        a[0] = (lane & 2) ? add2(a[1], oa1) : add2(a[0], oa0);
        b[0] = (lane & 2) ? add2(b[1], ob1) : add2(b[0], ob0);
    }
    {
        u64 oa0 = __shfl_xor_sync(0xffffffffu, a[0], 1);
        u64 ob0 = __shfl_xor_sync(0xffffffffu, b[0], 1);
        ra = add2(a[0], oa0);
        rb = add2(b[0], ob0);
    }
}

__global__ void __launch_bounds__(512, 1) k_main(
    const float* __restrict__ ho_bias,
    const int*   __restrict__ edges,
    const int*   __restrict__ et,
    float*       __restrict__ out)
{
    extern __shared__ float sm[];
    {
        const float4* src = reinterpret_cast<const float4*>(g_hoT);
        float4* dst = reinterpret_cast<float4*>(sm + S_HO);
        for (int i = threadIdx.x; i < (3 * NP * DD * HOSTRIDE) / 4; i += blockDim.x) dst[i] = src[i];
    }
    for (int i = threadIdx.x; i < 3 * NP * DD; i += blockDim.x)  sm[S_HOB + i] = ho_bias[i];
    __syncthreads();

    const int lane = threadIdx.x & 31;
    const int wid  = blockIdx.x * (blockDim.x >> 5) + (threadIdx.x >> 5);
    const int nw   = gridDim.x * (blockDim.x >> 5);

    int pre[PBLK + 1];
    pre[0] = 0;
#pragma unroll
    for (int b = 0; b < PBLK; b++) pre[b + 1] = pre[b] + __ldg(&g_cnt4[b]);
    const int total = pre[PBLK];

    const int b4 = (lane >> 4) & 1, b3 = (lane >> 3) & 1, b2 = (lane >> 2) & 1,
              b1 = (lane >> 1) & 1, b0 = lane & 1;
    const bool alive = (b0 == 0) && !(b1 && b2 && (b4 | b3));
    const int sid = 7 * b4 + (b4 ? 3 * b3 : 4 * b3) + 2 * b2 + b1;

#pragma unroll 1
    for (int u = wid; u < total; u += nw) {
        int bi = 0;
#pragma unroll
        for (int b = 1; b < PBLK; b++) bi += (u >= pre[b]);
        const int local = u - pre[bi];
        const int* gp = g_groups + bi * GCAP + local * 4;
        int ids[4];
#pragma unroll
        for (int b = 0; b < 4; b++) ids[b] = gp[b];
        int vmask = 1;
#pragma unroll
        for (int b = 1; b < 4; b++) {
            if (ids[b] >= 0) vmask |= (1 << b);
            else ids[b] = ids[0];
        }
        const int ty0 = __ldg(et + ids[0] * 3 + 0);
        const int ty1 = __ldg(et + ids[0] * 3 + 1);
        const int ty2 = __ldg(et + ids[0] * 3 + 2);
        const int ty[3] = {ty0, ty1, ty2};

        int nd[4][3];
#pragma unroll
        for (int b = 0; b < 4; b++)
#pragma unroll
            for (int s = 0; s < 3; s++)
                nd[b][s] = __ldg(edges + ids[b] * 3 + s);

        // ===== stage 1 replaced by T-table lookups (12 LDG.128 + 24 pk2) =====
        u64 t01[3][4], t23[3][4];
#pragma unroll
        for (int s = 0; s < 3; s++) {
            float4 e0 = __ldg(reinterpret_cast<const float4*>(g_T + (nd[0][s] * NP + ty[s]) * RR) + lane);
            float4 e1 = __ldg(reinterpret_cast<const float4*>(g_T + (nd[1][s] * NP + ty[s]) * RR) + lane);
            float4 e2 = __ldg(reinterpret_cast<const float4*>(g_T + (nd[2][s] * NP + ty[s]) * RR) + lane);
            float4 e3 = __ldg(reinterpret_cast<const float4*>(g_T + (nd[3][s] * NP + ty[s]) * RR) + lane);
            t01[s][0] = pk2(e0.x, e1.x); t01[s][1] = pk2(e0.y, e1.y);
            t01[s][2] = pk2(e0.z, e1.z); t01[s][3] = pk2(e0.w, e1.w);
            t23[s][0] = pk2(e2.x, e3.x); t23[s][1] = pk2(e2.y, e3.y);
            t23[s][2] = pk2(e2.z, e3.z); t23[s][3] = pk2(e2.w, e3.w);
        }

        // ===== stage 2: packed FMA + interleaved trees (R12 structure) =======
#pragma unroll
        for (int s = 0; s < 3; s++) {
            const int jj = (s == 0) ? 1 : 0;
            const int kk = (s == 2) ? 1 : 2;
            u64 f01[4], f23[4];
#pragma unroll
            for (int c = 0; c < 4; c++) {
                f01[c] = mul2(t01[jj][c], t01[kk][c]);
                f23[c] = mul2(t23[jj][c], t23[kk][c]);
            }
            const float* wh = sm + S_HO + (s * NP + ty[s]) * DD * HOSTRIDE;
            const float* hb = sm + S_HOB + (s * NP + ty[s]) * DD;
            u64 ms01[DD], ms23[DD];
#pragma unroll
            for (int d = 0; d < DD; d++) {
                float4 w = reinterpret_cast<const float4*>(wh + d * HOSTRIDE)[lane];
                u64 wx = dup2(w.x), wy = dup2(w.y), wz = dup2(w.z), ww = dup2(w.w);
                u64 m0 = mul2(f01[0], wx);
                m0 = fma2(f01[1], wy, m0);
                m0 = fma2(f01[2], wz, m0);
                ms01[d] = fma2(f01[3], ww, m0);
                u64 m1 = mul2(f23[0], wx);
                m1 = fma2(f23[1], wy, m1);
                m1 = fma2(f23[2], wz, m1);
                ms23[d] = fma2(f23[3], ww, m1);
            }
            u64 r01, r23;
            tree13p2(ms01, ms23, lane, r01, r23);
            if (alive) {
                float bias = hb[sid];
                float lo, hi;
                up2(lo, hi, r01);
                atomicAdd(out + nd[0][s] * DD + sid, lo + bias);
                if (vmask & 2) atomicAdd(out + nd[1][s] * DD + sid, hi + bias);
                up2(lo, hi, r23);
                if (vmask & 4) atomicAdd(out + nd[2][s] * DD + sid, lo + bias);
                if (vmask & 8) atomicAdd(out + nd[3][s] * DD + sid, hi + bias);
            }
        }
    }
}

extern "C" void kernel_launch(void* const* d_in, const int* in_sizes, int n_in,
                              void* d_out, int out_size) {
    const float* nodes      = (const float*)d_in[0];
    const float* bp_params  = (const float*)d_in[1];
    const float* bp_bias    = (const float*)d_in[2];
    const float* ho_params  = (const float*)d_in[3];
    const float* ho_bias    = (const float*)d_in[4];
    const int*   edges      = (const int*)d_in[5];
    const int*   edge_types = (const int*)d_in[6];
    float* out = (float*)d_out;

    int sms = 0;
    cudaDeviceGetAttribute(&sms, cudaDevAttrMultiProcessorCount, 0);
    if (sms <= 0) sms = 148;
    cudaFuncSetAttribute(k_main, cudaFuncAttributeMaxDynamicSharedMemorySize, S_TOT * 4);

    k_prep<<<PREPB, 1024>>>(edge_types, nodes, bp_params, bp_bias, ho_params, out);
    k_main<<<sms, 512, S_TOT * 4>>>(ho_bias, edges, edge_types, out);
}

// round 15
// speedup vs baseline: 1.3485x; 1.3485x over previous
#include <cuda_runtime.h>

#define NN 4096
#define EE 16384
#define DD 13
#define RR 128
#define NP 4
#define HOSTRIDE 132
#define PBLK 8
#define PREPB 152
#define EPB  (EE / PBLK)
#define GCAP 2304

typedef unsigned long long u64;

__device__ int   g_groups[PBLK * GCAP];
__device__ int   g_cnt4[PBLK];
__device__ __align__(16) float g_T[NN * NP * RR];          // 8 MB stage-1 table
__device__ __align__(16) float g_hoT[3 * NP * DD * HOSTRIDE];

// k_main smem layout (floats)
#define S_HO   0
#define S_HOB  (3 * NP * DD * HOSTRIDE)
#define S_TOT  (S_HOB + 3 * NP * DD)      // 20748 floats ~ 83 KB

// ---------------- f32x2 packed helpers --------------------------------------
__device__ __forceinline__ u64 pk2(float lo, float hi) {
    u64 r; asm("mov.b64 %0,{%1,%2};" : "=l"(r) : "f"(lo), "f"(hi)); return r;
}
__device__ __forceinline__ u64 dup2(float v) {
    u64 r; asm("mov.b64 %0,{%1,%1};" : "=l"(r) : "f"(v)); return r;
}
__device__ __forceinline__ void up2(float& lo, float& hi, u64 v) {
    asm("mov.b64 {%0,%1},%2;" : "=f"(lo), "=f"(hi) : "l"(v));
}
__device__ __forceinline__ u64 fma2(u64 a, u64 b, u64 c) {
    u64 d; asm("fma.rn.f32x2 %0,%1,%2,%3;" : "=l"(d) : "l"(a), "l"(b), "l"(c)); return d;
}
__device__ __forceinline__ u64 mul2(u64 a, u64 b) {
    u64 d; asm("mul.rn.f32x2 %0,%1,%2;" : "=l"(d) : "l"(a), "l"(b)); return d;
}
__device__ __forceinline__ u64 add2(u64 a, u64 b) {
    u64 d; asm("add.rn.f32x2 %0,%1,%2;" : "=l"(d) : "l"(a), "l"(b)); return d;
}

// ---- prep: blocks 0-7 bucket-sort; blocks 8-151 build the stage-1 table T ---
__global__ void __launch_bounds__(1024, 1) k_prep(const int* __restrict__ et,
                                                  const float* __restrict__ nodes,
                                                  const float* __restrict__ bp_params,
                                                  const float* __restrict__ bp_bias,
                                                  const float* __restrict__ ho_params,
                                                  float* __restrict__ out) {
    __shared__ float s_bp[NP * DD * RR + NP * RR];
    __shared__ int hist[64], bstart[64], cursor[64], gb[64], sc[64], sg[64];
    __shared__ short sorted[EPB];
    __shared__ unsigned char keys[EPB], skey[EPB];
    const int tid = threadIdx.x;
    const int bi  = blockIdx.x;
    const int lane = tid & 31;
    const int warp = tid >> 5;

    // shared jobs split over all 152 blocks
    {
        const int per = (NN * DD + PREPB - 1) / PREPB;
        const int o0 = bi * per;
        int o1 = o0 + per; if (o1 > NN * DD) o1 = NN * DD;
        for (int i = o0 + tid; i < o1; i += 1024) out[i] = 0.f;
    }
    {
        const int totalho = 3 * NP * RR * DD;   // 19968
        for (int i = bi * 1024 + tid; i < totalho; i += PREPB * 1024) {
            int d  = i % DD;
            int rd = i / DD;
            int r  = rd & (RR - 1);
            int sp = rd >> 7;
            g_hoT[(sp * DD + d) * HOSTRIDE + r] = ho_params[i];
        }
    }

    if (bi >= PBLK) {
        // ---- T-table compute: 4096 batches over 144 blocks x 32 warps -------
        for (int i = tid; i < NP * DD * RR; i += 1024) s_bp[i] = bp_params[i];
        for (int i = tid; i < NP * RR; i += 1024)      s_bp[NP * DD * RR + i] = bp_bias[i];
        __syncthreads();

        for (int bb = (bi - PBLK) * 32 + warp; bb < 4096; bb += (PREPB - PBLK) * 32) {
            const int ty = bb >> 10;
            const int n0 = (bb & 1023) << 2;
            const float* w = s_bp + ty * DD * RR;
            float4 bias = reinterpret_cast<const float4*>(s_bp + NP * DD * RR + ty * RR)[lane];
            float4 a0 = bias, a1 = bias, a2 = bias, a3 = bias;
#pragma unroll
            for (int d = 0; d < DD; d++) {
                float4 wv = reinterpret_cast<const float4*>(w + d * RR)[lane];
                float n0v = __ldg(nodes + (n0 + 0) * DD + d);
                float n1v = __ldg(nodes + (n0 + 1) * DD + d);
                float n2v = __ldg(nodes + (n0 + 2) * DD + d);
                float n3v = __ldg(nodes + (n0 + 3) * DD + d);
                a0.x = fmaf(n0v, wv.x, a0.x); a0.y = fmaf(n0v, wv.y, a0.y);
                a0.z = fmaf(n0v, wv.z, a0.z); a0.w = fmaf(n0v, wv.w, a0.w);
                a1.x = fmaf(n1v, wv.x, a1.x); a1.y = fmaf(n1v, wv.y, a1.y);
                a1.z = fmaf(n1v, wv.z, a1.z); a1.w = fmaf(n1v, wv.w, a1.w);
                a2.x = fmaf(n2v, wv.x, a2.x); a2.y = fmaf(n2v, wv.y, a2.y);
                a2.z = fmaf(n2v, wv.z, a2.z); a2.w = fmaf(n2v, wv.w, a2.w);
                a3.x = fmaf(n3v, wv.x, a3.x); a3.y = fmaf(n3v, wv.y, a3.y);
                a3.z = fmaf(n3v, wv.z, a3.z); a3.w = fmaf(n3v, wv.w, a3.w);
            }
            a0.x = fmaxf(a0.x, 0.f); a0.y = fmaxf(a0.y, 0.f); a0.z = fmaxf(a0.z, 0.f); a0.w = fmaxf(a0.w, 0.f);
            a1.x = fmaxf(a1.x, 0.f); a1.y = fmaxf(a1.y, 0.f); a1.z = fmaxf(a1.z, 0.f); a1.w = fmaxf(a1.w, 0.f);
            a2.x = fmaxf(a2.x, 0.f); a2.y = fmaxf(a2.y, 0.f); a2.z = fmaxf(a2.z, 0.f); a2.w = fmaxf(a2.w, 0.f);
            a3.x = fmaxf(a3.x, 0.f); a3.y = fmaxf(a3.y, 0.f); a3.z = fmaxf(a3.z, 0.f); a3.w = fmaxf(a3.w, 0.f);
            reinterpret_cast<float4*>(g_T + ((n0 + 0) * NP + ty) * RR)[lane] = a0;
            reinterpret_cast<float4*>(g_T + ((n0 + 1) * NP + ty) * RR)[lane] = a1;
            reinterpret_cast<float4*>(g_T + ((n0 + 2) * NP + ty) * RR)[lane] = a2;
            reinterpret_cast<float4*>(g_T + ((n0 + 3) * NP + ty) * RR)[lane] = a3;
        }
        return;
    }

    // ---- bucket sort (blocks 0-7) --------------------------------------------
    const int base = bi * EPB;
    for (int i = tid; i < GCAP; i += 1024) g_groups[bi * GCAP + i] = -1;

    if (tid < 64) hist[tid] = 0;
    __syncthreads();
    for (int i = tid; i < EPB; i += 1024) {
        int e = base + i;
        int k = __ldg(et + e * 3) * 16 + __ldg(et + e * 3 + 1) * 4 + __ldg(et + e * 3 + 2);
        keys[i] = (unsigned char)k;
        atomicAdd(&hist[k], 1);
    }
    __syncthreads();
    if (tid < 64) { sc[tid] = hist[tid]; sg[tid] = (hist[tid] + 3) >> 2; }
    __syncthreads();
    for (int off = 1; off < 64; off <<= 1) {
        int v1 = 0, v2 = 0;
        if (tid >= off && tid < 64) { v1 = sc[tid - off]; v2 = sg[tid - off]; }
        __syncthreads();
        if (tid >= off && tid < 64) { sc[tid] += v1; sg[tid] += v2; }
        __syncthreads();
    }
    if (tid < 64) {
        bstart[tid] = sc[tid] - hist[tid];
        cursor[tid] = sc[tid] - hist[tid];
        gb[tid]     = sg[tid] - ((hist[tid] + 3) >> 2);
        if (tid == 63) g_cnt4[bi] = sg[63];
    }
    __syncthreads();
    for (int i = tid; i < EPB; i += 1024) {
        int k = keys[i];
        int pos = atomicAdd(&cursor[k], 1);
        sorted[pos] = (short)i;
        skey[pos] = (unsigned char)k;
    }
    __syncthreads();
    for (int i = tid; i < EPB; i += 1024) {
        int k = skey[i];
        int r = i - bstart[k];
        g_groups[bi * GCAP + gb[k] * 4 + r] = base + (int)sorted[i];
    }
}

// ---- interleaved packed warp reduction of 2x13 f32x2 streams ----------------
__device__ __forceinline__ void tree13p2(u64* a, u64* b, int lane, u64& ra, u64& rb) {
    {
        u64 oa[13], ob[13];
#pragma unroll
        for (int i = 0; i < 13; i++) { oa[i] = __shfl_xor_sync(0xffffffffu, a[i], 16);
                                       ob[i] = __shfl_xor_sync(0xffffffffu, b[i], 16); }
        if (lane & 16) {
#pragma unroll
            for (int i = 0; i < 6; i++) { a[i] = add2(a[i + 7], oa[i + 7]); b[i] = add2(b[i + 7], ob[i + 7]); }
        } else {
#pragma unroll
            for (int i = 0; i < 7; i++) { a[i] = add2(a[i], oa[i]); b[i] = add2(b[i], ob[i]); }
        }
    }
    {
        u64 oa[7], ob[7];
#pragma unroll
        for (int i = 0; i < 7; i++) { oa[i] = __shfl_xor_sync(0xffffffffu, a[i], 8);
                                      ob[i] = __shfl_xor_sync(0xffffffffu, b[i], 8); }
        if (!(lane & 16)) {
            if (lane & 8) { a[0] = add2(a[4], oa[4]); a[1] = add2(a[5], oa[5]); a[2] = add2(a[6], oa[6]);
                            b[0] = add2(b[4], ob[4]); b[1] = add2(b[5], ob[5]); b[2] = add2(b[6], ob[6]); }
            else { a[0] = add2(a[0], oa[0]); a[1] = add2(a[1], oa[1]); a[2] = add2(a[2], oa[2]); a[3] = add2(a[3], oa[3]);
                   b[0] = add2(b[0], ob[0]); b[1] = add2(b[1], ob[1]); b[2] = add2(b[2], ob[2]); b[3] = add2(b[3], ob[3]); }
        } else {
            if (lane & 8) { a[0] = add2(a[3], oa[3]); a[1] = add2(a[4], oa[4]); a[2] = add2(a[5], oa[5]);
                            b[0] = add2(b[3], ob[3]); b[1] = add2(b[4], ob[4]); b[2] = add2(b[5], ob[5]); }
            else { a[0] = add2(a[0], oa[0]); a[1] = add2(a[1], oa[1]); a[2] = add2(a[2], oa[2]);
                   b[0] = add2(b[0], ob[0]); b[1] = add2(b[1], ob[1]); b[2] = add2(b[2], ob[2]); }
        }
    }
    {
        u64 oa[4], ob[4];
#pragma unroll
        for (int i = 0; i < 4; i++) { oa[i] = __shfl_xor_sync(0xffffffffu, a[i], 4);
                                      ob[i] = __shfl_xor_sync(0xffffffffu, b[i], 4); }
        bool four = ((lane & 24) == 0);
        if (lane & 4) {
            a[0] = add2(a[2], oa[2]); b[0] = add2(b[2], ob[2]);
            if (four) { a[1] = add2(a[3], oa[3]); b[1] = add2(b[3], ob[3]); }
        } else {
            a[0] = add2(a[0], oa[0]); a[1] = add2(a[1], oa[1]);
            b[0] = add2(b[0], ob[0]); b[1] = add2(b[1], ob[1]);
        }
    }
    {
        u64 oa0 = __shfl_xor_sync(0xffffffffu, a[0], 2);
        u64 oa1 = __shfl_xor_sync(0xffffffffu, a[1], 2);
        u64 ob0 = __shfl_xor_sync(0xffffffffu, b[0], 2);
        u64 ob1 = __shfl_xor_sync(0xffffffffu, b[1], 2);
        a[0] = (lane & 2) ? add2(a[1], oa1) : add2(a[0], oa0);
        b[0] = (lane & 2) ? add2(b[1], ob1) : add2(b[0], ob0);
    }
    {
        u64 oa0 = __shfl_xor_sync(0xffffffffu, a[0], 1);
        u64 ob0 = __shfl_xor_sync(0xffffffffu, b[0], 1);
        ra = add2(a[0], oa0);
        rb = add2(b[0], ob0);
    }
}

__global__ void __launch_bounds__(512, 1) k_main(
    const float* __restrict__ ho_bias,
    const int*   __restrict__ edges,
    const int*   __restrict__ et,
    float*       __restrict__ out)
{
    extern __shared__ float sm[];
    {
        const float4* src = reinterpret_cast<const float4*>(g_hoT);
        float4* dst = reinterpret_cast<float4*>(sm + S_HO);
        for (int i = threadIdx.x; i < (3 * NP * DD * HOSTRIDE) / 4; i += blockDim.x) dst[i] = src[i];
    }
    for (int i = threadIdx.x; i < 3 * NP * DD; i += blockDim.x)  sm[S_HOB + i] = ho_bias[i];
    __syncthreads();

    const int lane = threadIdx.x & 31;
    const int wid  = blockIdx.x * (blockDim.x >> 5) + (threadIdx.x >> 5);
    const int nw   = gridDim.x * (blockDim.x >> 5);

    int pre[PBLK + 1];
    pre[0] = 0;
#pragma unroll
    for (int b = 0; b < PBLK; b++) pre[b + 1] = pre[b] + __ldg(&g_cnt4[b]);
    const int total = pre[PBLK];

    const int b4 = (lane >> 4) & 1, b3 = (lane >> 3) & 1, b2 = (lane >> 2) & 1,
              b1 = (lane >> 1) & 1, b0 = lane & 1;
    const bool alive = (b0 == 0) && !(b1 && b2 && (b4 | b3));
    const int sid = 7 * b4 + (b4 ? 3 * b3 : 4 * b3) + 2 * b2 + b1;

#pragma unroll 1
    for (int u = wid; u < total; u += nw) {
        int bi = 0;
#pragma unroll
        for (int b = 1; b < PBLK; b++) bi += (u >= pre[b]);
        const int local = u - pre[bi];
        const int* gp = g_groups + bi * GCAP + local * 4;
        int ids[4];
#pragma unroll
        for (int b = 0; b < 4; b++) ids[b] = gp[b];
        int vmask = 1;
#pragma unroll
        for (int b = 1; b < 4; b++) {
            if (ids[b] >= 0) vmask |= (1 << b);
            else ids[b] = ids[0];
        }
        const int ty0 = __ldg(et + ids[0] * 3 + 0);
        const int ty1 = __ldg(et + ids[0] * 3 + 1);
        const int ty2 = __ldg(et + ids[0] * 3 + 2);
        const int ty[3] = {ty0, ty1, ty2};

        int nd[4][3];
#pragma unroll
        for (int b = 0; b < 4; b++)
#pragma unroll
            for (int s = 0; s < 3; s++)
                nd[b][s] = __ldg(edges + ids[b] * 3 + s);

        // ===== stage 1 via T-table lookups (12 LDG.128 + 24 pk2) =============
        u64 t01[3][4], t23[3][4];
#pragma unroll
        for (int s = 0; s < 3; s++) {
            float4 e0 = __ldg(reinterpret_cast<const float4*>(g_T + (nd[0][s] * NP + ty[s]) * RR) + lane);
            float4 e1 = __ldg(reinterpret_cast<const float4*>(g_T + (nd[1][s] * NP + ty[s]) * RR) + lane);
            float4 e2 = __ldg(reinterpret_cast<const float4*>(g_T + (nd[2][s] * NP + ty[s]) * RR) + lane);
            float4 e3 = __ldg(reinterpret_cast<const float4*>(g_T + (nd[3][s] * NP + ty[s]) * RR) + lane);
            t01[s][0] = pk2(e0.x, e1.x); t01[s][1] = pk2(e0.y, e1.y);
            t01[s][2] = pk2(e0.z, e1.z); t01[s][3] = pk2(e0.w, e1.w);
            t23[s][0] = pk2(e2.x, e3.x); t23[s][1] = pk2(e2.y, e3.y);
            t23[s][2] = pk2(e2.z, e3.z); t23[s][3] = pk2(e2.w, e3.w);
        }

        // ===== stage 2: packed FMA + interleaved trees =======================
#pragma unroll
        for (int s = 0; s < 3; s++) {
            const int jj = (s == 0) ? 1 : 0;
            const int kk = (s == 2) ? 1 : 2;
            u64 f01[4], f23[4];
#pragma unroll
            for (int c = 0; c < 4; c++) {
                f01[c] = mul2(t01[jj][c], t01[kk][c]);
                f23[c] = mul2(t23[jj][c], t23[kk][c]);
            }
            const float* wh = sm + S_HO + (s * NP + ty[s]) * DD * HOSTRIDE;
            const float* hb = sm + S_HOB + (s * NP + ty[s]) * DD;
            u64 ms01[DD], ms23[DD];
#pragma unroll
            for (int d = 0; d < DD; d++) {
                float4 w = reinterpret_cast<const float4*>(wh + d * HOSTRIDE)[lane];
                u64 wx = dup2(w.x), wy = dup2(w.y), wz = dup2(w.z), ww = dup2(w.w);
                u64 m0 = mul2(f01[0], wx);
                m0 = fma2(f01[1], wy, m0);
                m0 = fma2(f01[2], wz, m0);
                ms01[d] = fma2(f01[3], ww, m0);
                u64 m1 = mul2(f23[0], wx);
                m1 = fma2(f23[1], wy, m1);
                m1 = fma2(f23[2], wz, m1);
                ms23[d] = fma2(f23[3], ww, m1);
            }
            u64 r01, r23;
            tree13p2(ms01, ms23, lane, r01, r23);
            if (alive) {
                float bias = hb[sid];
                float lo, hi;
                up2(lo, hi, r01);
                atomicAdd(out + nd[0][s] * DD + sid, lo + bias);
                if (vmask & 2) atomicAdd(out + nd[1][s] * DD + sid, hi + bias);
                up2(lo, hi, r23);
                if (vmask & 4) atomicAdd(out + nd[2][s] * DD + sid, lo + bias);
                if (vmask & 8) atomicAdd(out + nd[3][s] * DD + sid, hi + bias);
            }
        }
    }
}

extern "C" void kernel_launch(void* const* d_in, const int* in_sizes, int n_in,
                              void* d_out, int out_size) {
    const float* nodes      = (const float*)d_in[0];
    const float* bp_params  = (const float*)d_in[1];
    const float* bp_bias    = (const float*)d_in[2];
    const float* ho_params  = (const float*)d_in[3];
    const float* ho_bias    = (const float*)d_in[4];
    const int*   edges      = (const int*)d_in[5];
    const int*   edge_types = (const int*)d_in[6];
    float* out = (float*)d_out;

    int sms = 0;
    cudaDeviceGetAttribute(&sms, cudaDevAttrMultiProcessorCount, 0);
    if (sms <= 0) sms = 148;
    cudaFuncSetAttribute(k_main, cudaFuncAttributeMaxDynamicSharedMemorySize, S_TOT * 4);

    k_prep<<<PREPB, 1024>>>(edge_types, nodes, bp_params, bp_bias, ho_params, out);
    k_main<<<sms, 512, S_TOT * 4>>>(ho_bias, edges, edge_types, out);
}